// round 1
// baseline (speedup 1.0000x reference)
#include <cuda_runtime.h>
#include <math.h>

#define NN 50000
#define EE 800000
#define EPSW 1e-5f

// ---------------- scratch (device globals, no allocation) ----------------
__device__ float g_deg[NN];
__device__ float g_logdeg[NN];
__device__ float g_amp[NN];
__device__ float g_att[NN];
__device__ float g_logsum;
__device__ int   g_rowptr[NN + 1];
__device__ int   g_cursor[NN];
__device__ int   g_col[EE];
__device__ float g_h0[(size_t)NN * 256];   // ping
__device__ float g_h1[(size_t)NN * 256];   // pong
__device__ float g_aggs[(size_t)NN * 1024]; // [N, 4*din] (din<=256)
__device__ float g_colsum[256];
__device__ float g_colsumsq[256];
__device__ float g_s[256];   // BN-affine scale of current layer input
__device__ float g_t[256];   // BN-affine shift
__device__ float g_wc2[64 * 10];
__device__ float g_bc2[10];

// ---------------- init ----------------
__global__ void k_init() {
    int i = blockIdx.x * blockDim.x + threadIdx.x;
    if (i < NN) g_deg[i] = 0.f;
    if (i < 256) { g_s[i] = 1.f; g_t[i] = 0.f; }
    if (i == 0) g_logsum = 0.f;
}

__global__ void k_degcnt(const int* __restrict__ ei) {
    int e = blockIdx.x * blockDim.x + threadIdx.x;
    if (e < EE) atomicAdd(&g_deg[ei[EE + e]], 1.f);
}

__global__ void k_logdeg() {
    int n = blockIdx.x * blockDim.x + threadIdx.x;
    float ld = 0.f;
    if (n < NN) { ld = log1pf(g_deg[n]); g_logdeg[n] = ld; }
    __shared__ float sh[256];
    sh[threadIdx.x] = ld;
    __syncthreads();
    for (int off = 128; off; off >>= 1) {
        if (threadIdx.x < off) sh[threadIdx.x] += sh[threadIdx.x + off];
        __syncthreads();
    }
    if (threadIdx.x == 0) atomicAdd(&g_logsum, sh[0]);
}

__global__ void k_scalers() {
    int n = blockIdx.x * blockDim.x + threadIdx.x;
    if (n >= NN) return;
    float delta = g_logsum / (float)NN;
    float ld = g_logdeg[n];
    g_amp[n] = ld / delta;
    g_att[n] = (ld > 0.f) ? delta / fmaxf(ld, 1e-6f) : 1.f;
}

// single-block exclusive scan of deg -> rowptr (and cursor copy)
__global__ void k_scan() {
    __shared__ int wsum[32];
    __shared__ int carry_s;
    int tid = threadIdx.x, lane = tid & 31, wid = tid >> 5;
    if (tid == 0) carry_s = 0;
    __syncthreads();
    for (int base = 0; base < NN; base += 1024) {
        int i = base + tid;
        int v = (i < NN) ? (int)g_deg[i] : 0;
        int x = v;
        #pragma unroll
        for (int off = 1; off < 32; off <<= 1) {
            int y = __shfl_up_sync(0xffffffffu, x, off);
            if (lane >= off) x += y;
        }
        if (lane == 31) wsum[wid] = x;
        __syncthreads();
        if (wid == 0) {
            int w = wsum[lane];
            #pragma unroll
            for (int off = 1; off < 32; off <<= 1) {
                int y = __shfl_up_sync(0xffffffffu, w, off);
                if (lane >= off) w += y;
            }
            wsum[lane] = w;
        }
        __syncthreads();
        int incl = x + (wid > 0 ? wsum[wid - 1] : 0);
        int carry = carry_s;
        if (i < NN) {
            int ex = carry + incl - v;
            g_rowptr[i] = ex;
            g_cursor[i] = ex;
        }
        __syncthreads();
        if (tid == 1023) carry_s = carry + incl;
        __syncthreads();
    }
    if (tid == 0) g_rowptr[NN] = carry_s;
}

__global__ void k_scatter(const int* __restrict__ ei) {
    int e = blockIdx.x * blockDim.x + threadIdx.x;
    if (e >= EE) return;
    int dst = ei[EE + e];
    int pos = atomicAdd(&g_cursor[dst], 1);
    g_col[pos] = ei[e];
}

// ---------------- aggregation (atomic-free, CSR) ----------------
// warp per (node, 32-channel chunk). Applies BN-affine (s,t) of previous layer
// on the fly. Writes aggs[n, 4*DIN] = [mean | min | max | std].
template <int DIN>
__global__ void k_agg(const float* __restrict__ in) {
    const int CH = DIN / 32;
    int warp = (blockIdx.x * blockDim.x + threadIdx.x) >> 5;
    int lane = threadIdx.x & 31;
    if (warp >= NN * CH) return;
    int n = warp / CH;
    int c = (warp % CH) * 32 + lane;
    float s = g_s[c], t = g_t[c];
    int beg = g_rowptr[n], end = g_rowptr[n + 1];
    float sum = 0.f, ss = 0.f, mn = INFINITY, mx = -INFINITY;
    for (int j = beg; j < end; j++) {
        int src = g_col[j];
        float v = in[(size_t)src * DIN + c];
        v = fmaf(s, v, t);
        sum += v; ss = fmaf(v, v, ss);
        mn = fminf(mn, v); mx = fmaxf(mx, v);
    }
    float deg = (float)(end - beg);
    float cnt = fmaxf(deg, 1.f);
    float mean = sum / cnt;
    float var = fmaxf(ss / cnt - mean * mean, 0.f);
    float sd = sqrtf(var + EPSW);
    bool has = end > beg;
    mn = has ? mn : 0.f;
    mx = has ? mx : 0.f;
    float* ag = g_aggs + (size_t)n * 4 * DIN;
    ag[c] = mean;
    ag[DIN + c] = mn;
    ag[2 * DIN + c] = mx;
    ag[3 * DIN + c] = sd;
}

__global__ void k_zerostats() {
    int c = threadIdx.x;
    if (c < 256) { g_colsum[c] = 0.f; g_colsumsq[c] = 0.f; }
}

// ---------------- fused PNA GEMM ----------------
// C[n,o] = relu( affine(in)@W[0:d] + A@W[d:5d] + amp[n]*(A@W[5d:9d])
//               + att[n]*(A@W[9d:13d]) + b[o] )
// Also accumulates column sum / sumsq of the ReLU output for BN.
template <int DIN, int DOUT>
__launch_bounds__(256)
__global__ void k_gemm(const float* __restrict__ in, const float* __restrict__ W,
                       const float* __restrict__ bias, float* __restrict__ out) {
    __shared__ float As[16][68];
    __shared__ float Bs1[16][64];
    __shared__ float Bs2[16][64];
    __shared__ float Bs3[16][64];
    __shared__ float scs[64], scss[64];

    const int tid = threadIdx.x;
    const int tx = tid & 15, ty = tid >> 4;
    const int m0 = blockIdx.x * 64;
    const int n0 = blockIdx.y * 64;
    const int la_m = tid >> 2;
    const int la_k = (tid & 3) * 4;
    const int lb_k = tid >> 4;
    const int lb_n = (tid & 15) * 4;

    float acc1[16], acc2[16], acc3[16];
    #pragma unroll
    for (int i = 0; i < 16; i++) { acc1[i] = 0.f; acc2[i] = 0.f; acc3[i] = 0.f; }

    // ---- phase X: K over DIN, affine(in) vs W rows [0,DIN) ----
    for (int k0 = 0; k0 < DIN; k0 += 16) {
        int row = m0 + la_m;
        float4 av = make_float4(0.f, 0.f, 0.f, 0.f);
        if (row < NN)
            av = *reinterpret_cast<const float4*>(in + (size_t)row * DIN + k0 + la_k);
        int kc = k0 + la_k;
        av.x = fmaf(g_s[kc + 0], av.x, g_t[kc + 0]);
        av.y = fmaf(g_s[kc + 1], av.y, g_t[kc + 1]);
        av.z = fmaf(g_s[kc + 2], av.z, g_t[kc + 2]);
        av.w = fmaf(g_s[kc + 3], av.w, g_t[kc + 3]);
        As[la_k + 0][la_m] = av.x;
        As[la_k + 1][la_m] = av.y;
        As[la_k + 2][la_m] = av.z;
        As[la_k + 3][la_m] = av.w;
        float4 bv = *reinterpret_cast<const float4*>(
            W + (size_t)(k0 + lb_k) * DOUT + n0 + lb_n);
        *reinterpret_cast<float4*>(&Bs1[lb_k][lb_n]) = bv;
        __syncthreads();
        #pragma unroll
        for (int kk = 0; kk < 16; kk++) {
            float4 a = *reinterpret_cast<float4*>(&As[kk][ty * 4]);
            float4 b = *reinterpret_cast<float4*>(&Bs1[kk][tx * 4]);
            float ar[4] = {a.x, a.y, a.z, a.w};
            float br[4] = {b.x, b.y, b.z, b.w};
            #pragma unroll
            for (int i = 0; i < 4; i++)
                #pragma unroll
                for (int j = 0; j < 4; j++)
                    acc1[i * 4 + j] = fmaf(ar[i], br[j], acc1[i * 4 + j]);
        }
        __syncthreads();
    }

    // ---- phase AGG: K over 4*DIN, shared A-tile, 3 weight streams ----
    for (int k0 = 0; k0 < 4 * DIN; k0 += 16) {
        int row = m0 + la_m;
        float4 av = make_float4(0.f, 0.f, 0.f, 0.f);
        if (row < NN)
            av = *reinterpret_cast<const float4*>(
                g_aggs + (size_t)row * 4 * DIN + k0 + la_k);
        As[la_k + 0][la_m] = av.x;
        As[la_k + 1][la_m] = av.y;
        As[la_k + 2][la_m] = av.z;
        As[la_k + 3][la_m] = av.w;
        int kr = k0 + lb_k;
        float4 b1 = *reinterpret_cast<const float4*>(
            W + (size_t)(DIN + kr) * DOUT + n0 + lb_n);
        float4 b2 = *reinterpret_cast<const float4*>(
            W + (size_t)(5 * DIN + kr) * DOUT + n0 + lb_n);
        float4 b3 = *reinterpret_cast<const float4*>(
            W + (size_t)(9 * DIN + kr) * DOUT + n0 + lb_n);
        *reinterpret_cast<float4*>(&Bs1[lb_k][lb_n]) = b1;
        *reinterpret_cast<float4*>(&Bs2[lb_k][lb_n]) = b2;
        *reinterpret_cast<float4*>(&Bs3[lb_k][lb_n]) = b3;
        __syncthreads();
        #pragma unroll
        for (int kk = 0; kk < 16; kk++) {
            float4 a = *reinterpret_cast<float4*>(&As[kk][ty * 4]);
            float4 v1 = *reinterpret_cast<float4*>(&Bs1[kk][tx * 4]);
            float4 v2 = *reinterpret_cast<float4*>(&Bs2[kk][tx * 4]);
            float4 v3 = *reinterpret_cast<float4*>(&Bs3[kk][tx * 4]);
            float ar[4] = {a.x, a.y, a.z, a.w};
            float b1r[4] = {v1.x, v1.y, v1.z, v1.w};
            float b2r[4] = {v2.x, v2.y, v2.z, v2.w};
            float b3r[4] = {v3.x, v3.y, v3.z, v3.w};
            #pragma unroll
            for (int i = 0; i < 4; i++)
                #pragma unroll
                for (int j = 0; j < 4; j++) {
                    acc1[i * 4 + j] = fmaf(ar[i], b1r[j], acc1[i * 4 + j]);
                    acc2[i * 4 + j] = fmaf(ar[i], b2r[j], acc2[i * 4 + j]);
                    acc3[i * 4 + j] = fmaf(ar[i], b3r[j], acc3[i * 4 + j]);
                }
        }
        __syncthreads();
    }

    // ---- epilogue: combine scalers, bias, ReLU, store, column stats ----
    if (tid < 64) { scs[tid] = 0.f; scss[tid] = 0.f; }
    __syncthreads();
    float cls[4] = {0.f, 0.f, 0.f, 0.f};
    float clss[4] = {0.f, 0.f, 0.f, 0.f};
    #pragma unroll
    for (int i = 0; i < 4; i++) {
        int row = m0 + ty * 4 + i;
        if (row >= NN) continue;
        float amp = g_amp[row], att = g_att[row];
        #pragma unroll
        for (int j = 0; j < 4; j++) {
            int colg = n0 + tx * 4 + j;
            float v = acc1[i * 4 + j] + amp * acc2[i * 4 + j] +
                      att * acc3[i * 4 + j] + bias[colg];
            v = fmaxf(v, 0.f);
            out[(size_t)row * DOUT + colg] = v;
            cls[j] += v;
            clss[j] = fmaf(v, v, clss[j]);
        }
    }
    #pragma unroll
    for (int j = 0; j < 4; j++) {
        atomicAdd(&scs[tx * 4 + j], cls[j]);
        atomicAdd(&scss[tx * 4 + j], clss[j]);
    }
    __syncthreads();
    if (tid < 64) {
        atomicAdd(&g_colsum[n0 + tid], scs[tid]);
        atomicAdd(&g_colsumsq[n0 + tid], scss[tid]);
    }
}

__global__ void k_stats(const float* __restrict__ gamma,
                        const float* __restrict__ beta, int dout) {
    int c = blockIdx.x * blockDim.x + threadIdx.x;
    if (c >= dout) return;
    float mean = g_colsum[c] / (float)NN;
    float var = fmaxf(g_colsumsq[c] / (float)NN - mean * mean, 0.f);
    float sc = gamma[c] * rsqrtf(var + EPSW);
    g_s[c] = sc;
    g_t[c] = beta[c] - mean * sc;
}

// ---------------- classifier ----------------
__global__ void k_foldcls(const float* __restrict__ Wc, const float* __restrict__ bc) {
    int tid = threadIdx.x;
    if (tid < 640) {
        int c = tid / 10;
        g_wc2[tid] = g_s[c] * Wc[tid];
    }
    if (tid < 10) {
        float acc = bc[tid];
        for (int c = 0; c < 64; c++) acc = fmaf(g_t[c], Wc[c * 10 + tid], acc);
        g_bc2[tid] = acc;
    }
}

__global__ void k_cls(const float* __restrict__ r, float* __restrict__ out) {
    __shared__ float w[640];
    __shared__ float b[10];
    int tid = threadIdx.x;
    for (int i = tid; i < 640; i += blockDim.x) w[i] = g_wc2[i];
    if (tid < 10) b[tid] = g_bc2[tid];
    __syncthreads();
    int warp = (blockIdx.x * blockDim.x + tid) >> 5;
    int lane = tid & 31;
    if (warp >= NN) return;
    float v0 = r[(size_t)warp * 64 + lane];
    float v1 = r[(size_t)warp * 64 + 32 + lane];
    float acc[10];
    #pragma unroll
    for (int j = 0; j < 10; j++)
        acc[j] = v0 * w[lane * 10 + j] + v1 * w[(32 + lane) * 10 + j];
    #pragma unroll
    for (int off = 16; off; off >>= 1)
        #pragma unroll
        for (int j = 0; j < 10; j++)
            acc[j] += __shfl_xor_sync(0xffffffffu, acc[j], off);
    if (lane < 10) out[(size_t)warp * 10 + lane] = acc[lane] + b[lane];
}

// ---------------- launch ----------------
extern "C" void kernel_launch(void* const* d_in, const int* in_sizes, int n_in,
                              void* d_out, int out_size) {
    const float* x  = (const float*)d_in[0];
    const int*   ei = (const int*)d_in[1];
    const float* W1 = (const float*)d_in[2];
    const float* b1 = (const float*)d_in[3];
    const float* ga1 = (const float*)d_in[4];
    const float* be1 = (const float*)d_in[5];
    const float* W2 = (const float*)d_in[6];
    const float* b2 = (const float*)d_in[7];
    const float* ga2 = (const float*)d_in[8];
    const float* be2 = (const float*)d_in[9];
    const float* W3 = (const float*)d_in[10];
    const float* b3 = (const float*)d_in[11];
    const float* ga3 = (const float*)d_in[12];
    const float* be3 = (const float*)d_in[13];
    const float* W4 = (const float*)d_in[14];
    const float* b4 = (const float*)d_in[15];
    const float* ga4 = (const float*)d_in[16];
    const float* be4 = (const float*)d_in[17];
    const float* Wc = (const float*)d_in[18];
    const float* bc = (const float*)d_in[19];
    float* out = (float*)d_out;

    float *p_h0, *p_h1;
    cudaGetSymbolAddress((void**)&p_h0, g_h0);
    cudaGetSymbolAddress((void**)&p_h1, g_h1);

    // graph preprocessing (recomputed every call)
    k_init<<<(NN + 255) / 256, 256>>>();
    k_degcnt<<<EE / 256, 256>>>(ei);
    k_logdeg<<<(NN + 255) / 256, 256>>>();
    k_scalers<<<(NN + 255) / 256, 256>>>();
    k_scan<<<1, 1024>>>();
    k_scatter<<<EE / 256, 256>>>(ei);

    const int MB = (NN + 63) / 64;

    // layer 1: 64 -> 128  (input x, identity affine)
    k_agg<64><<<((size_t)NN * 64 + 255) / 256, 256>>>(x);
    k_zerostats<<<1, 256>>>();
    k_gemm<64, 128><<<dim3(MB, 2), 256>>>(x, W1, b1, p_h0);
    k_stats<<<1, 256>>>(ga1, be1, 128);

    // layer 2: 128 -> 256
    k_agg<128><<<((size_t)NN * 128 + 255) / 256, 256>>>(p_h0);
    k_zerostats<<<1, 256>>>();
    k_gemm<128, 256><<<dim3(MB, 4), 256>>>(p_h0, W2, b2, p_h1);
    k_stats<<<1, 256>>>(ga2, be2, 256);

    // layer 3: 256 -> 128
    k_agg<256><<<((size_t)NN * 256 + 255) / 256, 256>>>(p_h1);
    k_zerostats<<<1, 256>>>();
    k_gemm<256, 128><<<dim3(MB, 2), 256>>>(p_h1, W3, b3, p_h0);
    k_stats<<<1, 256>>>(ga3, be3, 128);

    // layer 4: 128 -> 64
    k_agg<128><<<((size_t)NN * 128 + 255) / 256, 256>>>(p_h0);
    k_zerostats<<<1, 256>>>();
    k_gemm<128, 64><<<dim3(MB, 1), 256>>>(p_h0, W4, b4, p_h1);
    k_stats<<<1, 256>>>(ga4, be4, 64);

    // classifier
    k_foldcls<<<1, 640>>>(Wc, bc);
    k_cls<<<((size_t)NN * 32 + 255) / 256, 256>>>(p_h1, out);
}